// round 4
// baseline (speedup 1.0000x reference)
#include <cuda_runtime.h>

// T=4 tables, N=1,000,000 rows, D=4, B=16384 bags, TOTAL=819,200 lookups/table.
// out[t*B+s] = b + sum_{i: seg[t,i]=s} dot(tables[t, idx[t,i]], W)
//
// R4: A/B experiment against the L1tex divergent-replay floor (2.07 cyc/line).
//  Kernel A (elements [0, 2*TOTAL)): half-warp broadcast gather, nL=2 per LDG.
//  Kernel B (elements [2*TOTAL, 4*TOTAL)): divergent gather, 8 elements/thread.

#define EMB_T      4
#define EMB_N      1000000
#define EMB_B      16384
#define EMB_TOTAL  819200

__global__ void init_out_kernel(float* __restrict__ out,
                                const float* __restrict__ b,
                                int n) {
    int i = blockIdx.x * blockDim.x + threadIdx.x;
    if (i < n) out[i] = __ldg(b);
}

__device__ __forceinline__ unsigned long long policy_evict_last() {
    unsigned long long p;
    asm volatile("createpolicy.fractional.L2::evict_last.b64 %0, 1.0;" : "=l"(p));
    return p;
}
__device__ __forceinline__ unsigned long long policy_evict_first() {
    unsigned long long p;
    asm volatile("createpolicy.fractional.L2::evict_first.b64 %0, 1.0;" : "=l"(p));
    return p;
}
__device__ __forceinline__ float4 ldg_hot_f4(const float4* p, unsigned long long pol) {
    float4 r;
    asm volatile("ld.global.nc.L2::cache_hint.v4.f32 {%0,%1,%2,%3}, [%4], %5;"
                 : "=f"(r.x), "=f"(r.y), "=f"(r.z), "=f"(r.w) : "l"(p), "l"(pol));
    return r;
}
__device__ __forceinline__ int4 ldg_stream_i4(const int4* p, unsigned long long pol) {
    int4 r;
    asm volatile("ld.global.nc.L2::cache_hint.v4.b32 {%0,%1,%2,%3}, [%4], %5;"
                 : "=r"(r.x), "=r"(r.y), "=r"(r.z), "=r"(r.w) : "l"(p), "l"(pol));
    return r;
}

// ───────────────────────── Kernel A: half-warp broadcast (nL=2 per LDG) ──────
// 1 element per thread; warp loops 16x, each LDG.128 has lanes 0-15 on one row
// and lanes 16-31 on another -> 2 cache lines per instruction.
__global__ __launch_bounds__(256)
void embbag_bcast_kernel(const float4* __restrict__ tables,
                         const float*  __restrict__ W,
                         const int*    __restrict__ indices,
                         const int*    __restrict__ segs,
                         float*        __restrict__ out)
{
    const int g = blockIdx.x * blockDim.x + threadIdx.x;   // element id [0, 2*TOTAL)
    const int t = g / EMB_TOTAL;                           // tables 0..1
    const unsigned lane = threadIdx.x & 31u;

    const unsigned long long pol_hot = policy_evict_last();
    const float4 w = __ldg((const float4*)W);

    const int idx = __ldg(indices + g);
    const int seg = __ldg(segs + g);

    const float4* tbl = tables + (size_t)t * EMB_N;
    const unsigned grp = lane & 16u;     // 0 for lanes 0-15, 16 for lanes 16-31

    float v = 0.f;
    #pragma unroll
    for (int m = 0; m < 16; m++) {
        const int ridx = __shfl_sync(0xffffffffu, idx, m + (int)grp);
        const float4 r = ldg_hot_f4(tbl + ridx, pol_hot);
        const float vm = r.x * w.x + r.y * w.y + r.z * w.z + r.w * w.w;
        if ((lane & 15u) == (unsigned)m) v = vm;
    }

    // warp segmented inclusive scan (segments sorted -> contiguous runs)
    #pragma unroll
    for (int off = 1; off < 32; off <<= 1) {
        const float up  = __shfl_up_sync(0xffffffffu, v, off);
        const int   sup = __shfl_up_sync(0xffffffffu, seg, off);
        if (lane >= (unsigned)off && sup == seg) v += up;
    }
    const int next_seg = __shfl_down_sync(0xffffffffu, seg, 1);
    if (lane == 31u || next_seg != seg) {
        atomicAdd(out + t * EMB_B + seg, v);
    }
}

// ───────────────────────── Kernel B: divergent, 8 elements/thread ────────────
__global__ __launch_bounds__(256)
void embbag_pool8_kernel(const float4* __restrict__ tables,
                         const float*  __restrict__ W,
                         const int*    __restrict__ indices,
                         const int*    __restrict__ segs,
                         float*        __restrict__ out)
{
    const int g0 = 2 * EMB_TOTAL + (blockIdx.x * blockDim.x + threadIdx.x) * 8;
    const int t = g0 / EMB_TOTAL;                          // tables 2..3
    const unsigned lane = threadIdx.x & 31u;

    const unsigned long long pol_hot    = policy_evict_last();
    const unsigned long long pol_stream = policy_evict_first();
    const float4 w = __ldg((const float4*)W);

    const int4 ia = ldg_stream_i4((const int4*)(indices + g0), pol_stream);
    const int4 ib = ldg_stream_i4((const int4*)(indices + g0 + 4), pol_stream);
    const int4 sa = ldg_stream_i4((const int4*)(segs + g0), pol_stream);
    const int4 sb = ldg_stream_i4((const int4*)(segs + g0 + 4), pol_stream);

    int s[8] = {sa.x, sa.y, sa.z, sa.w, sb.x, sb.y, sb.z, sb.w};
    int ix[8] = {ia.x, ia.y, ia.z, ia.w, ib.x, ib.y, ib.z, ib.w};

    const float4* tbl = tables + (size_t)t * EMB_N;
    float v[8];
    #pragma unroll
    for (int m = 0; m < 8; m++) {
        const float4 r = ldg_hot_f4(tbl + ix[m], pol_hot);
        v[m] = r.x * w.x + r.y * w.y + r.z * w.z + r.w * w.w;
    }

    float* obase = out + t * EMB_B;
    const bool all_same = (s[0] == s[7]);

    // sorted => membership by value equality with endpoints
    float head = 0.f, tail = 0.f;
    #pragma unroll
    for (int m = 0; m < 8; m++) {
        if (s[m] == s[0])           head += v[m];
        else if (s[m] == s[7])      tail += v[m];
        else                        atomicAdd(obase + s[m], v[m]);  // interior run (rare)
    }

    // warp segmented scan over window aggregates
    const int prev_s7 = __shfl_up_sync(0xffffffffu, s[7], 1);
    const bool cont = (lane > 0u && prev_s7 == s[0]);
    int f = (all_same && cont) ? 0 : 1;
    float x = all_same ? head : tail;
    #pragma unroll
    for (int off = 1; off < 32; off <<= 1) {
        const float xo = __shfl_up_sync(0xffffffffu, x, off);
        const int   fo = __shfl_up_sync(0xffffffffu, f, off);
        if (lane >= (unsigned)off) {
            if (!f) x += xo;
            f |= fo;
        }
    }

    const float x_prev = __shfl_up_sync(0xffffffffu, x, 1);
    if (!all_same) {
        float ht = head;
        if (cont) ht += x_prev;
        atomicAdd(obase + s[0], ht);
    }
    const int next_s0 = __shfl_down_sync(0xffffffffu, s[0], 1);
    if (lane == 31u || next_s0 != s[7]) {
        atomicAdd(obase + s[7], x);
    }
}

extern "C" void kernel_launch(void* const* d_in, const int* in_sizes, int n_in,
                              void* d_out, int out_size) {
    const float4* tables  = (const float4*)d_in[0];
    const float*  W       = (const float*)d_in[1];
    const float*  b       = (const float*)d_in[2];
    const int*    indices = (const int*)d_in[3];
    const int*    segs    = (const int*)d_in[4];
    float*        out     = (float*)d_out;

    const int n_out = EMB_T * EMB_B;
    init_out_kernel<<<(n_out + 255) / 256, 256>>>(out, b, n_out);

    // A: elements [0, 2*TOTAL), 1 elem/thread
    const int nA = 2 * EMB_TOTAL;                      // 1,638,400
    embbag_bcast_kernel<<<nA / 256, 256>>>(tables, W, indices, segs, out);

    // B: elements [2*TOTAL, 4*TOTAL), 8 elems/thread
    const int nB_threads = (2 * EMB_TOTAL) / 8;        // 204,800
    embbag_pool8_kernel<<<nB_threads / 256, 256>>>(tables, W, indices, segs, out);
}

// round 5
// speedup vs baseline: 1.5816x; 1.5816x over previous
#include <cuda_runtime.h>

// T=4 tables, N=1,000,000 rows, D=4, B=16384 bags, TOTAL=819,200 lookups/table.
// out[t*B+s] = b + sum_{i: seg[t,i]=s} dot(tables[t, idx[t,i]], W)
// (Linear(4,1) folded into pooling. Gather is L1tex-wavefront-bound at ~2 cyc/row;
//  this kernel sits at that floor with minimal instruction overhead.)

#define EMB_T      4
#define EMB_N      1000000
#define EMB_B      16384
#define EMB_TOTAL  819200

__global__ void init_out_kernel(float4* __restrict__ out,
                                const float* __restrict__ b,
                                int n4) {
    int i = blockIdx.x * blockDim.x + threadIdx.x;
    if (i < n4) {
        const float bb = __ldg(b);
        out[i] = make_float4(bb, bb, bb, bb);
    }
}

__device__ __forceinline__ unsigned long long policy_evict_last() {
    unsigned long long p;
    asm volatile("createpolicy.fractional.L2::evict_last.b64 %0, 1.0;" : "=l"(p));
    return p;
}
__device__ __forceinline__ unsigned long long policy_evict_first() {
    unsigned long long p;
    asm volatile("createpolicy.fractional.L2::evict_first.b64 %0, 1.0;" : "=l"(p));
    return p;
}
__device__ __forceinline__ float4 ldg_hot_f4(const float4* p, unsigned long long pol) {
    float4 r;
    asm volatile("ld.global.nc.L2::cache_hint.v4.f32 {%0,%1,%2,%3}, [%4], %5;"
                 : "=f"(r.x), "=f"(r.y), "=f"(r.z), "=f"(r.w) : "l"(p), "l"(pol));
    return r;
}
__device__ __forceinline__ int4 ldg_stream_i4(const int4* p, unsigned long long pol) {
    int4 r;
    asm volatile("ld.global.nc.L2::cache_hint.v4.b32 {%0,%1,%2,%3}, [%4], %5;"
                 : "=r"(r.x), "=r"(r.y), "=r"(r.z), "=r"(r.w) : "l"(p), "l"(pol));
    return r;
}

__global__ __launch_bounds__(256)
void embbag_pool8_kernel(const float4* __restrict__ tables,   // [T*N] rows
                         const float*  __restrict__ W,        // [4]
                         const int*    __restrict__ indices,  // [T*TOTAL]
                         const int*    __restrict__ segs,     // [T*TOTAL]
                         float*        __restrict__ out)      // [T*B]
{
    const int g0 = (blockIdx.x * blockDim.x + threadIdx.x) * 8;   // first of 8 elems
    // TOTAL % 256 == 0 => a warp's 256 elements share one table.
    const int t = g0 / EMB_TOTAL;
    const unsigned lane = threadIdx.x & 31u;

    const unsigned long long pol_hot    = policy_evict_last();
    const unsigned long long pol_stream = policy_evict_first();
    const float4 w = __ldg((const float4*)W);

    const int4 ia = ldg_stream_i4((const int4*)(indices + g0), pol_stream);
    const int4 ib = ldg_stream_i4((const int4*)(indices + g0 + 4), pol_stream);
    const int4 sa = ldg_stream_i4((const int4*)(segs + g0), pol_stream);
    const int4 sb = ldg_stream_i4((const int4*)(segs + g0 + 4), pol_stream);

    const int s[8]  = {sa.x, sa.y, sa.z, sa.w, sb.x, sb.y, sb.z, sb.w};
    const int ix[8] = {ia.x, ia.y, ia.z, ia.w, ib.x, ib.y, ib.z, ib.w};

    const float4* tbl = tables + (size_t)t * EMB_N;
    // 8 independent gathers in flight per thread (MLP=8).
    float v[8];
    #pragma unroll
    for (int m = 0; m < 8; m++) {
        const float4 r = ldg_hot_f4(tbl + ix[m], pol_hot);
        v[m] = r.x * w.x + r.y * w.y + r.z * w.z + r.w * w.w;
    }

    float* obase = out + t * EMB_B;
    const bool all_same = (s[0] == s[7]);

    // Sorted segments: every element equals the first, the last, or is interior.
    float head = 0.f, tail = 0.f;
    #pragma unroll
    for (int m = 0; m < 8; m++) {
        if (s[m] == s[0])        head += v[m];
        else if (s[m] == s[7])   tail += v[m];
        else                     atomicAdd(obase + s[m], v[m]);   // interior run (rare)
    }

    // Warp segmented inclusive scan over per-thread tail aggregates.
    const int prev_s7 = __shfl_up_sync(0xffffffffu, s[7], 1);
    const bool cont = (lane > 0u && prev_s7 == s[0]);
    int f = (all_same && cont) ? 0 : 1;
    float x = all_same ? head : tail;
    #pragma unroll
    for (int off = 1; off < 32; off <<= 1) {
        const float xo = __shfl_up_sync(0xffffffffu, x, off);
        const int   fo = __shfl_up_sync(0xffffffffu, f, off);
        if (lane >= (unsigned)off) {
            if (!f) x += xo;
            f |= fo;
        }
    }

    // Carry previous lane's inclusive value into this thread's head run.
    const float x_prev = __shfl_up_sync(0xffffffffu, x, 1);
    if (!all_same) {
        float ht = head;
        if (cont) ht += x_prev;
        atomicAdd(obase + s[0], ht);
    }
    // Flush tail-inclusive value if the run ends at this thread.
    const int next_s0 = __shfl_down_sync(0xffffffffu, s[0], 1);
    if (lane == 31u || next_s0 != s[7]) {
        atomicAdd(obase + s[7], x);
    }
}

extern "C" void kernel_launch(void* const* d_in, const int* in_sizes, int n_in,
                              void* d_out, int out_size) {
    const float4* tables  = (const float4*)d_in[0];
    const float*  W       = (const float*)d_in[1];
    const float*  b       = (const float*)d_in[2];
    const int*    indices = (const int*)d_in[3];
    const int*    segs    = (const int*)d_in[4];
    float*        out     = (float*)d_out;

    const int n4 = (EMB_T * EMB_B) / 4;                    // 16,384 float4 stores
    init_out_kernel<<<n4 / 256, 256>>>((float4*)out, b, n4);

    const int n_threads = (EMB_T * EMB_TOTAL) / 8;         // 409,600
    embbag_pool8_kernel<<<n_threads / 256, 256>>>(tables, W, indices, segs, out);
}

// round 6
// speedup vs baseline: 1.8931x; 1.1969x over previous
#include <cuda_runtime.h>

// T=4 tables, N=1,000,000 rows, D=4, B=16384 bags, TOTAL=819,200 lookups/table.
// out[t*B+s] = b + sum_{i: seg[t,i]=s} dot(tables[t, idx[t,i]], W)
//
// Linear(4,1) folded into pooling. The gather of 3.27M random 16B rows is bound
// by the L1tex within-LDG replay rate (~2.07 cyc per distinct line per SM) =
// ~45.8K cyc/SM; 4 elems/thread at 256 threads/block (32 regs, ~87% occ) is the
// measured-optimal configuration at that floor.

#define EMB_T      4
#define EMB_N      1000000
#define EMB_B      16384
#define EMB_TOTAL  819200

__global__ void init_out_kernel(float4* __restrict__ out,
                                const float* __restrict__ b,
                                int n4) {
    int i = blockIdx.x * blockDim.x + threadIdx.x;
    if (i < n4) {
        const float bb = __ldg(b);
        out[i] = make_float4(bb, bb, bb, bb);
    }
}

__device__ __forceinline__ unsigned long long policy_evict_last() {
    unsigned long long p;
    asm volatile("createpolicy.fractional.L2::evict_last.b64 %0, 1.0;" : "=l"(p));
    return p;
}
__device__ __forceinline__ unsigned long long policy_evict_first() {
    unsigned long long p;
    asm volatile("createpolicy.fractional.L2::evict_first.b64 %0, 1.0;" : "=l"(p));
    return p;
}
// Table row gather: keep hot in L2 across graph replays.
__device__ __forceinline__ float4 ldg_hot_f4(const float4* p, unsigned long long pol) {
    float4 r;
    asm volatile("ld.global.nc.L2::cache_hint.v4.f32 {%0,%1,%2,%3}, [%4], %5;"
                 : "=f"(r.x), "=f"(r.y), "=f"(r.z), "=f"(r.w) : "l"(p), "l"(pol));
    return r;
}
// Streamed indices/segments: don't pollute L2.
__device__ __forceinline__ int4 ldg_stream_i4(const int4* p, unsigned long long pol) {
    int4 r;
    asm volatile("ld.global.nc.L2::cache_hint.v4.b32 {%0,%1,%2,%3}, [%4], %5;"
                 : "=r"(r.x), "=r"(r.y), "=r"(r.z), "=r"(r.w) : "l"(p), "l"(pol));
    return r;
}

__global__ __launch_bounds__(256)
void embbag_pool4_kernel(const float4* __restrict__ tables,   // [T*N] rows
                         const float*  __restrict__ W,        // [4]
                         const int*    __restrict__ indices,  // [T*TOTAL]
                         const int*    __restrict__ segs,     // [T*TOTAL]
                         float*        __restrict__ out)      // [T*B]
{
    const int g0 = (blockIdx.x * blockDim.x + threadIdx.x) * 4;  // first of 4 elems
    // TOTAL % 128 == 0 => a thread's 4 elements (and a warp's 128) share one table.
    const int t = g0 / EMB_TOTAL;
    const unsigned lane = threadIdx.x & 31u;

    const unsigned long long pol_hot    = policy_evict_last();
    const unsigned long long pol_stream = policy_evict_first();

    const float4 w = __ldg((const float4*)W);

    const int4 idx = ldg_stream_i4((const int4*)(indices + g0), pol_stream);
    const int4 sg  = ldg_stream_i4((const int4*)(segs + g0), pol_stream);

    const float4* tbl = tables + (size_t)t * EMB_N;
    // 4 independent gathers in flight (MLP=4 per thread).
    const float4 r0 = ldg_hot_f4(tbl + idx.x, pol_hot);
    const float4 r1 = ldg_hot_f4(tbl + idx.y, pol_hot);
    const float4 r2 = ldg_hot_f4(tbl + idx.z, pol_hot);
    const float4 r3 = ldg_hot_f4(tbl + idx.w, pol_hot);

    const float v0 = r0.x * w.x + r0.y * w.y + r0.z * w.z + r0.w * w.w;
    const float v1 = r1.x * w.x + r1.y * w.y + r1.z * w.z + r1.w * w.w;
    const float v2 = r2.x * w.x + r2.y * w.y + r2.z * w.z + r2.w * w.w;
    const float v3 = r3.x * w.x + r3.y * w.y + r3.z * w.z + r3.w * w.w;

    float* obase = out + t * EMB_B;

    // ---- intra-thread run decomposition (segments are sorted) ----
    const bool e01 = (sg.x == sg.y);
    const bool e12 = (sg.y == sg.z);
    const bool e23 = (sg.z == sg.w);
    const bool all_same = e01 && e12 && e23;

    // head run (contains element 0), tail run (contains element 3)
    const float head_sum = v0 + (e01 ? (v1 + (e12 ? (v2 + (e23 ? v3 : 0.f)) : 0.f)) : 0.f);
    const float tail_sum = v3 + (e23 ? (v2 + (e12 ? (v1 + (e01 ? v0 : 0.f)) : 0.f)) : 0.f);

    // complete runs strictly inside the 4-window -> flush directly (rare)
    if (!e01 && !e12)           atomicAdd(obase + sg.y, v1);
    if (!e12 && !e23)           atomicAdd(obase + sg.z, v2);
    if (!e01 &&  e12 && !e23)   atomicAdd(obase + sg.y, v1 + v2);

    // ---- warp segmented scan over per-thread tail aggregates ----
    const int prev_s3 = __shfl_up_sync(0xffffffffu, sg.w, 1);
    // lane continues previous lane's run only if this thread is single-segment
    // and its segment matches the previous thread's last segment
    int f = (all_same && lane > 0u && prev_s3 == sg.x) ? 0 : 1;
    float x = tail_sum;
    #pragma unroll
    for (int off = 1; off < 32; off <<= 1) {
        const float xo = __shfl_up_sync(0xffffffffu, x, off);
        const int   fo = __shfl_up_sync(0xffffffffu, f, off);
        if (lane >= (unsigned)off) {
            if (!f) x += xo;
            f |= fo;
        }
    }

    // carry from previous lane's inclusive scan into this thread's head run
    const float x_prev = __shfl_up_sync(0xffffffffu, x, 1);
    if (!all_same) {
        float head_total = head_sum;
        if (lane > 0u && prev_s3 == sg.x) head_total += x_prev;
        atomicAdd(obase + sg.x, head_total);
    }

    // flush tail-inclusive value if the run ends here
    const int next_s0 = __shfl_down_sync(0xffffffffu, sg.x, 1);
    if (lane == 31u || next_s0 != sg.w) {
        atomicAdd(obase + sg.w, x);
    }
}

extern "C" void kernel_launch(void* const* d_in, const int* in_sizes, int n_in,
                              void* d_out, int out_size) {
    const float4* tables  = (const float4*)d_in[0];
    const float*  W       = (const float*)d_in[1];
    const float*  b       = (const float*)d_in[2];
    const int*    indices = (const int*)d_in[3];
    const int*    segs    = (const int*)d_in[4];
    float*        out     = (float*)d_out;

    const int n4 = (EMB_T * EMB_B) / 4;                    // 16,384 float4 stores
    init_out_kernel<<<n4 / 256, 256>>>((float4*)out, b, n4);

    const int n_threads = (EMB_T * EMB_TOTAL) / 4;         // 819,200
    embbag_pool4_kernel<<<n_threads / 256, 256>>>(tables, W, indices, segs, out);
}